// round 16
// baseline (speedup 1.0000x reference)
#include <cuda_runtime.h>
#include <cuda_bf16.h>
#include <cuda_fp16.h>
#include <math.h>

// ---------------------------------------------------------------------------
// Problem constants
// ---------------------------------------------------------------------------
#define NQ      6000
#define NBOX    3000
#define KMAX    80
#define CAP     256
#define KS      4
#define NCELL   64
#define RADIUS  0.1125f

#define GDIM    8
#define NCELLS  (GDIM*GDIM*GDIM)

#define K1TOT   6240     // layer1 GEMM K (6144 conv + 96 dense)
#define K2TOT   4160     // layer2 GEMM K (4096 conv + 64 dense)
#define SPLITK  4

// ---------------------------------------------------------------------------
// Device scratch
// ---------------------------------------------------------------------------
__device__ __align__(16) __half g_S[(size_t)NQ * K1TOT];
__device__ __align__(16) float g_x96[NQ * 96];
__device__ __align__(16) float g_ya[NQ * 64];
__device__ __align__(16) float g_yb[NQ * 64];
__device__ __align__(16) float g_ff[NQ * 4];
__device__ __align__(16) float g_part[SPLITK * NQ * 64];
__device__ __align__(16) __half g_Wt1[64 * K1TOT];   // [n][k] fp16, layer1
__device__ __align__(16) __half g_Wt2[64 * K2TOT];   // [n][k] fp16, layer2

__device__ int   g_fcnt[NQ];
__device__ int   g_fidx[NQ * KMAX];
__device__ int   g_fcell[NQ * KMAX];
__device__ __align__(16) float g_fcoef[(size_t)NQ * KMAX * 8];

__device__ int   g_ocnt[NQ];
__device__ int   g_oidx[NQ * KMAX];
__device__ int   g_ocell[NQ * KMAX];
__device__ __align__(16) float g_ocoef[(size_t)NQ * KMAX * 8];

// hash grids (0 = fluid/pos, 1 = box); counters self-re-zeroed in grid_scan2
__device__ int g_gcnt[2][NCELLS];
__device__ int g_gstart[2][NCELLS + 1];
__device__ int g_gcur[2][NCELLS];
__device__ int g_glistF[NQ];
__device__ int g_glistB[NBOX];

// ---------------------------------------------------------------------------
// Helpers
// ---------------------------------------------------------------------------
__device__ __forceinline__ float fsign(float x) {
    return (x > 0.f) ? 1.f : ((x < 0.f) ? -1.f : 0.f);
}

__device__ __forceinline__ int cell_coord(float x) {
    int c = (int)(x * (float)GDIM);
    return min(max(c, 0), GDIM - 1);
}

__device__ __forceinline__ void mma16816(float4& d, unsigned a0, unsigned a1,
                                         unsigned a2, unsigned a3,
                                         unsigned b0, unsigned b1) {
    asm volatile(
        "mma.sync.aligned.m16n8k16.row.col.f32.f16.f16.f32 "
        "{%0,%1,%2,%3}, {%4,%5,%6,%7}, {%8,%9}, {%0,%1,%2,%3};"
        : "+f"(d.x), "+f"(d.y), "+f"(d.z), "+f"(d.w)
        : "r"(a0), "r"(a1), "r"(a2), "r"(a3), "r"(b0), "r"(b1));
}

// ---------------------------------------------------------------------------
// Hash grid build
// ---------------------------------------------------------------------------
__global__ void grid_hist2(const float* __restrict__ pos, const float* __restrict__ box) {
    int g = blockIdx.y;
    const float* p = g ? box : pos;
    int n = g ? NBOX : NQ;
    int i = blockIdx.x * blockDim.x + threadIdx.x;
    if (i >= n) return;
    int cx = cell_coord(p[3 * i + 0]);
    int cy = cell_coord(p[3 * i + 1]);
    int cz = cell_coord(p[3 * i + 2]);
    atomicAdd(&g_gcnt[g][(cz * GDIM + cy) * GDIM + cx], 1);
}

__global__ void grid_scan2() {
    int g = blockIdx.x;
    __shared__ int s[NCELLS];
    int t = threadIdx.x;
    int v = g_gcnt[g][t];
    g_gcnt[g][t] = 0;          // reset for next replay (deterministic)
    s[t] = v;
    __syncthreads();
    for (int off = 1; off < NCELLS; off <<= 1) {
        int x = (t >= off) ? s[t - off] : 0;
        __syncthreads();
        s[t] += x;
        __syncthreads();
    }
    g_gstart[g][t + 1] = s[t];
    g_gcur[g][t] = s[t] - v;
    if (t == 0) g_gstart[g][0] = 0;
}

__global__ void grid_fill2(const float* __restrict__ pos, const float* __restrict__ box) {
    int g = blockIdx.y;
    const float* p = g ? box : pos;
    int n = g ? NBOX : NQ;
    int* list = g ? g_glistB : g_glistF;
    int i = blockIdx.x * blockDim.x + threadIdx.x;
    if (i >= n) return;
    int cx = cell_coord(p[3 * i + 0]);
    int cy = cell_coord(p[3 * i + 1]);
    int cz = cell_coord(p[3 * i + 2]);
    int slot = atomicAdd(&g_gcur[g][(cz * GDIM + cy) * GDIM + cx], 1);
    list[slot] = i;
}

// ---------------------------------------------------------------------------
// Neighbor search: 2 queries per block (threadIdx.y), both passes on blockIdx.y.
// blockDim (64, 2), grid (NQ/2, 2).
// ---------------------------------------------------------------------------
__global__ void nbr_grid2(const float* __restrict__ pos, const float* __restrict__ box) {
    int pass = blockIdx.y;
    const float* pin   = pass ? box : pos;
    const int*  glist  = pass ? g_glistB : g_glistF;
    const int*  gstart = g_gstart[pass];
    int selfExcl = pass ? 0 : 1;
    int* cnt_out  = pass ? g_ocnt  : g_fcnt;
    int* idx_out  = pass ? g_oidx  : g_fidx;
    int* cell_out = pass ? g_ocell : g_fcell;
    float* coef_out = pass ? g_ocoef : g_fcoef;

    int qy = threadIdx.y;                     // 0 or 1
    int i = blockIdx.x * 2 + qy;              // query index (< NQ by construction)
    __shared__ float sd2[2][CAP];
    __shared__ int   sj[2][CAP];
    __shared__ int   ssel[2][KMAX];
    __shared__ int   scnt[2], skeep[2];
    int tid = threadIdx.x;
    const int NT = 64;
    if (tid == 0) { scnt[qy] = 0; skeep[qy] = 0; }
    __syncthreads();

    float qx = pos[3 * i + 0], qyc = pos[3 * i + 1], qz = pos[3 * i + 2];
    const float R2 = RADIUS * RADIUS;

    int cx = cell_coord(qx), cy = cell_coord(qyc), cz = cell_coord(qz);
    int x0 = max(cx - 1, 0), x1 = min(cx + 1, GDIM - 1);
    int y0 = max(cy - 1, 0), y1 = min(cy + 1, GDIM - 1);
    int z0 = max(cz - 1, 0), z1 = min(cz + 1, GDIM - 1);

    for (int z = z0; z <= z1; z++) {
        for (int y = y0; y <= y1; y++) {
            int cbase = (z * GDIM + y) * GDIM;
            int b = gstart[cbase + x0];
            int e = gstart[cbase + x1 + 1];
            for (int t = b + tid; t < e; t += NT) {
                int j = glist[t];
                if (selfExcl && j == i) continue;
                float dx = pin[3 * j + 0] - qx;
                float dy = pin[3 * j + 1] - qyc;
                float dz = pin[3 * j + 2] - qz;
                float d2 = dx * dx + dy * dy + dz * dz;
                if (d2 <= R2) {
                    int p = atomicAdd(&scnt[qy], 1);
                    if (p < CAP) { sd2[qy][p] = d2; sj[qy][p] = j; }
                }
            }
        }
    }
    __syncthreads();

    int cnt = min(scnt[qy], CAP);
    int kcnt;
    if (cnt <= KMAX) {
        kcnt = cnt;
        for (int e = tid; e < cnt; e += NT) ssel[qy][e] = sj[qy][e];
    } else {
        kcnt = KMAX;
        for (int e = tid; e < cnt; e += NT) {
            float m2 = sd2[qy][e]; int mj = sj[qy][e]; int rank = 0;
            for (int q = 0; q < cnt; q++) {
                float o2 = sd2[qy][q];
                rank += (o2 < m2) || (o2 == m2 && sj[qy][q] < mj);
            }
            if (rank < KMAX) { int p = atomicAdd(&skeep[qy], 1); ssel[qy][p] = mj; }
        }
    }
    __syncthreads();
    if (tid == 0) cnt_out[i] = kcnt;

    const float EPS = 1e-12f;
    const float FP  = (float)(4.0 / 3.14159265358979323846);

    for (int k = tid; k < kcnt; k += NT) {
        int j = ssel[qy][k];
        float rx = (pin[3 * j + 0] - qx) / RADIUS;
        float ry = (pin[3 * j + 1] - qyc) / RADIUS;
        float rz = (pin[3 * j + 2] - qz) / RADIUS;

        float sq = rx * rx + ry * ry + rz * rz;
        float p1m = 1.0f - sq;
        float win = p1m * p1m * p1m;
        win = fminf(fmaxf(win, 0.f), 1.f);

        float nrm  = sqrtf(sq);
        float rxy2 = rx * rx + ry * ry;
        bool  polar = (1.25f * rz * rz) > rxy2;
        float s_pol = sqrtf(3.0f * nrm / (nrm + fabsf(rz) + EPS));
        float s_eq  = nrm / sqrtf(rxy2 + EPS);
        float xc = polar ? s_pol * rx : s_eq * rx;
        float yc = polar ? s_pol * ry : s_eq * ry;
        float zc = polar ? fsign(rz) * nrm : 1.5f * rz * s_eq;
        if (sq < 1e-12f) { xc = 0.f; yc = 0.f; zc = 0.f; }

        float rxy = sqrtf(xc * xc + yc * yc);
        float sx = (fabsf(xc) < EPS) ? EPS : xc;
        float sy = (fabsf(yc) < EPS) ? EPS : yc;
        float u1 = fsign(xc) * rxy;
        float v1 = u1 * FP * atanf(yc / sx);
        float v2 = fsign(yc) * rxy;
        float u2 = v2 * FP * atanf(xc / sy);
        float u, v;
        if (fabsf(xc) >= fabsf(yc)) { u = u1; v = v1; } else { u = u2; v = v2; }
        if (rxy < EPS) { u = 0.f; v = 0.f; }

        float gx = fminf(fmaxf((u  + 1.0f) * 0.5f * (float)(KS - 1), 0.f), (float)(KS - 1));
        float gy = fminf(fmaxf((v  + 1.0f) * 0.5f * (float)(KS - 1), 0.f), (float)(KS - 1));
        float gz = fminf(fmaxf((zc + 1.0f) * 0.5f * (float)(KS - 1), 0.f), (float)(KS - 1));
        int ix = min((int)floorf(gx), KS - 2);
        int iy = min((int)floorf(gy), KS - 2);
        int iz = min((int)floorf(gz), KS - 2);
        float tx = gx - (float)ix, ty = gy - (float)iy, tz = gz - (float)iz;

        int slot = i * KMAX + k;
        idx_out[slot]  = j;
        cell_out[slot] = (iz * KS + iy) * KS + ix;

        float wx[2] = {1.f - tx, tx};
        float wy[2] = {1.f - ty, ty};
        float wz[2] = {1.f - tz, tz};
        float* cf = coef_out + (size_t)slot * 8;
        #pragma unroll
        for (int dx = 0; dx < 2; dx++)
            #pragma unroll
            for (int dy = 0; dy < 2; dy++)
                #pragma unroll
                for (int dz = 0; dz < 2; dz++)
                    cf[dx * 4 + dy * 2 + dz] = wx[dx] * wy[dy] * wz[dz] * win;
    }
}

// ---------------------------------------------------------------------------
// convertW: build fp16 transposed weights Wt[n][k] for both HMMA layers.
// ---------------------------------------------------------------------------
__global__ void convertW(const float* __restrict__ c1w, const float* __restrict__ d1w,
                         const float* __restrict__ c2w, const float* __restrict__ d2w) {
    __shared__ float s[32][65];
    int t = blockIdx.x;
    const float *Wa, *Wb;
    __half* Wt;
    int K, Ka, k0;
    if (t < K1TOT / 32) {
        k0 = t * 32; K = K1TOT; Ka = 6144; Wa = c1w; Wb = d1w; Wt = g_Wt1;
    } else {
        k0 = (t - K1TOT / 32) * 32; K = K2TOT; Ka = 4096; Wa = c2w; Wb = d2w; Wt = g_Wt2;
    }
    int tid = threadIdx.x;
    #pragma unroll
    for (int i = 0; i < 8; i++) {
        int idx = tid + i * 256;          // 0..2047
        int row = idx >> 6;               // k offset 0..31
        int col = idx & 63;               // n
        int k = k0 + row;
        float v = (k < Ka) ? Wa[(size_t)k * 64 + col] : Wb[(size_t)(k - Ka) * 64 + col];
        s[row][col] = v;
    }
    __syncthreads();
    #pragma unroll
    for (int i = 0; i < 8; i++) {
        int idx = tid + i * 256;
        int n  = idx >> 5;                // 0..63
        int kk = idx & 31;
        Wt[(size_t)n * K + k0 + kk] = __float2half_rn(s[kk][n]);
    }
}

// ---------------------------------------------------------------------------
// prep: ff = [1,vel]; x96[:,64:96] = ff @ d0_w + d0_b
// ---------------------------------------------------------------------------
__global__ void prep_kernel(const float* __restrict__ vel,
                            const float* __restrict__ d0_w, const float* __restrict__ d0_b) {
    int i = blockIdx.x * blockDim.x + threadIdx.x;
    if (i >= NQ) return;
    float f1 = vel[i * 3 + 0], f2 = vel[i * 3 + 1], f3 = vel[i * 3 + 2];
    g_ff[i * 4 + 0] = 1.0f;
    g_ff[i * 4 + 1] = f1;
    g_ff[i * 4 + 2] = f2;
    g_ff[i * 4 + 3] = f3;
    #pragma unroll 8
    for (int o = 0; o < 32; o++) {
        g_x96[i * 96 + 64 + o] = d0_w[o] + f1 * d0_w[32 + o] + f2 * d0_w[64 + o]
                                 + f3 * d0_w[96 + o] + d0_b[o];
    }
}

// ---------------------------------------------------------------------------
// Merged first-block scatter: y=0 fluid/ff (F=4), y=1 box/box_feats (F=3).
// ---------------------------------------------------------------------------
__global__ void scatter_first(const float* __restrict__ box_feats) {
    int pass = blockIdx.y;
    const int F = pass ? 3 : 4;
    const int nF = 64 * F;
    const float* feats = pass ? box_feats : g_ff;
    const int* cnt  = pass ? g_ocnt  : g_fcnt;
    const int* nidx = pass ? g_oidx  : g_fidx;
    const int* ncel = pass ? g_ocell : g_fcell;
    const float* ncoef = pass ? g_ocoef : g_fcoef;
    __half* dst = g_S + (pass ? (size_t)NQ * 256 : 0);
    int ldS = pass ? 192 : 256;

    int i = blockIdx.x;
    extern __shared__ float shS[];            // 32 * nF floats (<= 32KB)
    __shared__ float shC[KMAX * 8];
    __shared__ int   shI[KMAX];
    __shared__ int   shCe[KMAX];
    int tid = threadIdx.x;
    const int NT = 128;

    for (int q = tid; q < 32 * nF; q += NT) shS[q] = 0.f;
    int c = cnt[i];
    for (int q = tid; q < c; q += NT) {
        shI[q]  = nidx[i * KMAX + q];
        shCe[q] = ncel[i * KMAX + q];
    }
    for (int q = tid; q < c * 8; q += NT)
        shC[q] = ncoef[(size_t)i * KMAX * 8 + q];
    __syncthreads();

    {
        int f = tid % F;
        int s = tid / F;
        if (s < 32) {
            int k0 = (c * s) / 32;
            int k1 = (c * (s + 1)) / 32;
            float* my = shS + s * nF;
            const int OFF[8] = {0, 16, 4, 20, 1, 17, 5, 21};
            for (int k = k0; k < k1; k++) {
                int j = shI[k];
                float vv = feats[(size_t)j * F + f];
                int base = shCe[k] * F + f;
                #pragma unroll
                for (int cc = 0; cc < 8; cc++)
                    my[base + OFF[cc] * F] += shC[k * 8 + cc] * vv;
            }
        }
    }
    __syncthreads();

    __half* drow = dst + (size_t)i * ldS;
    for (int q = tid * 2; q < nF; q += NT * 2) {
        float v0 = shS[q], v1 = shS[q + 1];
        #pragma unroll
        for (int s = 1; s < 32; s++) { v0 += shS[s * nF + q]; v1 += shS[s * nF + q + 1]; }
        *(__half2*)(drow + q) = __floats2half2_rn(v0, v1);
    }
}

// ---------------------------------------------------------------------------
// Persistent 32-col GEMM pair: y=0 cf (K=256), y=1 co (K=192). Writes g_x96.
// Each block loads sW once and grid-strides over row groups.
// ---------------------------------------------------------------------------
__global__ void gemm32_pair(const float* __restrict__ cf_w, const float* __restrict__ cf_b,
                            const float* __restrict__ co_w, const float* __restrict__ co_b) {
    int pass = blockIdx.y;
    int K = pass ? 192 : 256;
    const __half* A = g_S + (pass ? (size_t)NQ * 256 : 0);
    const float* W = pass ? co_w : cf_w;
    const float* b = pass ? co_b : cf_b;
    int ooff = pass ? 0 : 32;

    extern __shared__ float sW[];   // 32 * (K+1)
    int tid = threadIdx.x;
    int KP = K + 1;
    for (int q = tid; q < K * 32; q += blockDim.x) {
        int k = q >> 5, o = q & 31;
        sW[o * KP + k] = W[q];
    }
    __syncthreads();

    int wid = tid >> 5;
    int lane = tid & 31;
    for (int warp = blockIdx.x * 8 + wid; warp < NQ; warp += gridDim.x * 8) {
        const __half* Ar = A + (size_t)warp * K;

        float acc[32];
        #pragma unroll
        for (int o = 0; o < 32; o++) acc[o] = 0.f;

        for (int k = lane * 2; k < K; k += 64) {
            float2 a = __half22float2(*(const __half2*)(Ar + k));
            #pragma unroll
            for (int o = 0; o < 32; o++)
                acc[o] += a.x * sW[o * KP + k] + a.y * sW[o * KP + k + 1];
        }

        float myv = 0.f;
        #pragma unroll
        for (int o = 0; o < 32; o++) {
            float v = acc[o];
            v += __shfl_xor_sync(0xffffffffu, v, 16);
            v += __shfl_xor_sync(0xffffffffu, v, 8);
            v += __shfl_xor_sync(0xffffffffu, v, 4);
            v += __shfl_xor_sync(0xffffffffu, v, 2);
            v += __shfl_xor_sync(0xffffffffu, v, 1);
            if (lane == o) myv = v;
        }
        g_x96[(size_t)warp * 96 + ooff + lane] = myv + b[lane];
    }
}

// ---------------------------------------------------------------------------
// Tensor-core scatter: S_row[64,F] = CoefDense[64,80] @ NF[80,F] per particle.
// k-loop dynamically bounded at climit = ceil16(c).
// ---------------------------------------------------------------------------
#define PA 82   // smem pitch in halves (41 words)

template <int F>
__global__ void scatter_mma(const int* __restrict__ cnt, const int* __restrict__ nidx,
                            const int* __restrict__ ncell, const float* __restrict__ ncoef,
                            const float* __restrict__ feats,
                            __half* __restrict__ Sout, int ldS) {
    __shared__ __half sA[64 * PA];      // coef dense [cell][k]
    __shared__ __half sB[F * PA];       // feats transposed [f][k]
    __shared__ float shC[KMAX * 8];
    __shared__ int   shI[KMAX];

    int i = blockIdx.x;
    int tid = threadIdx.x;
    int warp = tid >> 5, lane = tid & 31;
    int g = lane >> 2, tq = lane & 3;

    int c = cnt[i];
    int climit = (c + 15) & ~15;        // MMA k-range (multiple of 16, <= 80)
    int words = climit >> 1;            // half2 words per row to zero

    unsigned* za = (unsigned*)sA;
    unsigned* zb = (unsigned*)sB;
    for (int q = tid; q < 64 * words; q += 128) {
        int r = q / words, w = q - r * words;
        za[r * (PA / 2) + w] = 0u;
    }
    for (int q = tid; q < F * words; q += 128) {
        int r = q / words, w = q - r * words;
        zb[r * (PA / 2) + w] = 0u;
    }

    for (int q = tid; q < c; q += 128) shI[q] = nidx[i * KMAX + q];
    for (int q = tid; q < c * 8; q += 128) shC[q] = ncoef[(size_t)i * KMAX * 8 + q];
    __syncthreads();

    {
        const int OFF[8] = {0, 16, 4, 20, 1, 17, 5, 21};
        __shared__ int shCe[KMAX];
        for (int q = tid; q < c; q += 128) shCe[q] = ncell[i * KMAX + q];
        __syncthreads();
        for (int t = tid; t < c * 8; t += 128) {
            int k = t >> 3, cc = t & 7;
            sA[(shCe[k] + OFF[cc]) * PA + k] = __float2half_rn(shC[t]);
        }
    }

    for (int k = warp; k < c; k += 4) {
        const float* fr = feats + (size_t)shI[k] * F;
        #pragma unroll
        for (int f = lane; f < F; f += 32)
            sB[f * PA + k] = __float2half_rn(fmaxf(fr[f], 0.f));
    }
    __syncthreads();

    float4 acc[F / 8];
    #pragma unroll
    for (int nj = 0; nj < F / 8; nj++) acc[nj] = make_float4(0.f, 0.f, 0.f, 0.f);

    for (int ks = 0; ks < climit; ks += 16) {
        int rbase = (warp * 16 + g) * PA + ks + 2 * tq;
        unsigned a0 = *(const unsigned*)&sA[rbase];
        unsigned a1 = *(const unsigned*)&sA[rbase + 8 * PA];
        unsigned a2 = *(const unsigned*)&sA[rbase + 8];
        unsigned a3 = *(const unsigned*)&sA[rbase + 8 * PA + 8];
        #pragma unroll
        for (int nj = 0; nj < F / 8; nj++) {
            int nbase = (nj * 8 + g) * PA + ks + 2 * tq;
            unsigned b0 = *(const unsigned*)&sB[nbase];
            unsigned b1 = *(const unsigned*)&sB[nbase + 8];
            mma16816(acc[nj], a0, a1, a2, a3, b0, b1);
        }
    }

    __half* dst = Sout + (size_t)i * ldS;
    int r0 = warp * 16 + g, r1 = r0 + 8;
    #pragma unroll
    for (int nj = 0; nj < F / 8; nj++) {
        int col = nj * 8 + 2 * tq;
        *(__half2*)(dst + r0 * F + col) = __floats2half2_rn(acc[nj].x, acc[nj].y);
        *(__half2*)(dst + r1 * F + col) = __floats2half2_rn(acc[nj].z, acc[nj].w);
    }
    if (tid < F)
        dst[64 * F + tid] = __float2half_rn(fmaxf(feats[(size_t)i * F + tid], 0.f));
}

// ---------------------------------------------------------------------------
// HMMA GEMM with split-K: grid (ceil(M/64), SPLITK). Raw partials to part.
// ---------------------------------------------------------------------------
#define PITCH 40

__global__ void gemm_hmma_sk(const __half* __restrict__ A, int M, int K,
                             const __half* __restrict__ Wt,
                             float* __restrict__ part) {
    __shared__ __half sA[2][64 * PITCH];
    __shared__ __half sB[2][64 * PITCH];

    int tid = threadIdx.x;
    int warp = tid >> 5, lane = tid & 31;
    int g = lane >> 2, tq = lane & 3;
    int wm = (warp & 1) * 32, wn = (warp >> 1) * 32;
    int bm = blockIdx.x * 64;

    int nt = K / 32;
    int tps = (nt + SPLITK - 1) / SPLITK;
    int t0 = blockIdx.y * tps;
    int t1 = min(t0 + tps, nt);
    float* out = part + (size_t)blockIdx.y * M * 64;

    int c0 = tid * 2, c1 = c0 + 1;
    int rA0 = c0 >> 2, ch0 = c0 & 3;
    int rA1 = c1 >> 2, ch1 = c1 & 3;
    bool ok0 = (bm + rA0) < M, ok1 = (bm + rA1) < M;
    const __half* Ab0 = A + (size_t)(bm + rA0) * K + ch0 * 8;
    const __half* Ab1 = A + (size_t)(bm + rA1) * K + ch1 * 8;
    const __half* Wb0 = Wt + (size_t)rA0 * K + ch0 * 8;
    const __half* Wb1 = Wt + (size_t)rA1 * K + ch1 * 8;

    float4 acc[2][4];
    #pragma unroll
    for (int i = 0; i < 2; i++)
        #pragma unroll
        for (int j = 0; j < 4; j++) acc[i][j] = make_float4(0.f, 0.f, 0.f, 0.f);

    const uint4 Z = make_uint4(0u, 0u, 0u, 0u);
    uint4 ra0, ra1, rb0, rb1;

    {
        int kt = t0 * 32;
        ra0 = ok0 ? *(const uint4*)(Ab0 + kt) : Z;
        ra1 = ok1 ? *(const uint4*)(Ab1 + kt) : Z;
        rb0 = *(const uint4*)(Wb0 + kt);
        rb1 = *(const uint4*)(Wb1 + kt);
    }
    *(uint4*)&sA[0][rA0 * PITCH + ch0 * 8] = ra0;
    *(uint4*)&sA[0][rA1 * PITCH + ch1 * 8] = ra1;
    *(uint4*)&sB[0][rA0 * PITCH + ch0 * 8] = rb0;
    *(uint4*)&sB[0][rA1 * PITCH + ch1 * 8] = rb1;
    __syncthreads();

    for (int t = t0; t < t1; t++) {
        int cur = (t - t0) & 1;
        if (t + 1 < t1) {
            int kt = (t + 1) * 32;
            ra0 = ok0 ? *(const uint4*)(Ab0 + kt) : Z;
            ra1 = ok1 ? *(const uint4*)(Ab1 + kt) : Z;
            rb0 = *(const uint4*)(Wb0 + kt);
            rb1 = *(const uint4*)(Wb1 + kt);
        }

        const __half* cA = sA[cur];
        const __half* cB = sB[cur];
        #pragma unroll
        for (int ks = 0; ks < 32; ks += 16) {
            unsigned af[2][4], bf[4][2];
            #pragma unroll
            for (int mi = 0; mi < 2; mi++) {
                int rbase = (wm + mi * 16 + g) * PITCH + ks + 2 * tq;
                af[mi][0] = *(const unsigned*)&cA[rbase];
                af[mi][1] = *(const unsigned*)&cA[rbase + 8 * PITCH];
                af[mi][2] = *(const unsigned*)&cA[rbase + 8];
                af[mi][3] = *(const unsigned*)&cA[rbase + 8 * PITCH + 8];
            }
            #pragma unroll
            for (int nj = 0; nj < 4; nj++) {
                int nbase = (wn + nj * 8 + g) * PITCH + ks + 2 * tq;
                bf[nj][0] = *(const unsigned*)&cB[nbase];
                bf[nj][1] = *(const unsigned*)&cB[nbase + 8];
            }
            #pragma unroll
            for (int mi = 0; mi < 2; mi++)
                #pragma unroll
                for (int nj = 0; nj < 4; nj++)
                    mma16816(acc[mi][nj], af[mi][0], af[mi][1], af[mi][2], af[mi][3],
                             bf[nj][0], bf[nj][1]);
        }

        if (t + 1 < t1) {
            int nxt = cur ^ 1;
            *(uint4*)&sA[nxt][rA0 * PITCH + ch0 * 8] = ra0;
            *(uint4*)&sA[nxt][rA1 * PITCH + ch1 * 8] = ra1;
            *(uint4*)&sB[nxt][rA0 * PITCH + ch0 * 8] = rb0;
            *(uint4*)&sB[nxt][rA1 * PITCH + ch1 * 8] = rb1;
            __syncthreads();
        }
    }

    #pragma unroll
    for (int mi = 0; mi < 2; mi++) {
        int r0 = bm + wm + mi * 16 + g;
        int r1 = r0 + 8;
        #pragma unroll
        for (int nj = 0; nj < 4; nj++) {
            int col = wn + nj * 8 + 2 * tq;
            float4 d = acc[mi][nj];
            if (r0 < M) *(float2*)&out[(size_t)r0 * 64 + col] = make_float2(d.x, d.y);
            if (r1 < M) *(float2*)&out[(size_t)r1 * 64 + col] = make_float2(d.z, d.w);
        }
    }
}

// ---------------------------------------------------------------------------
// combine4: out = sum(4 partials) + b1 + b2 (+ res)
// ---------------------------------------------------------------------------
__global__ void combine4(const float* __restrict__ part,
                         const float* __restrict__ b1, const float* __restrict__ b2,
                         const float* __restrict__ res, float* __restrict__ out, int M) {
    int idx = blockIdx.x * blockDim.x + threadIdx.x;
    if (idx >= M * 64) return;
    int c = idx & 63;
    size_t st = (size_t)M * 64;
    float v = part[idx] + part[st + idx] + part[2 * st + idx] + part[3 * st + idx]
              + b1[c] + b2[c];
    if (res) v += res[idx];
    out[idx] = v;
}

// ---------------------------------------------------------------------------
// Persistent small-O GEMM (final layer): W loaded once per block, grid-stride.
// ---------------------------------------------------------------------------
template <int O>
__global__ void gemm_small(const __half* __restrict__ A, int lda, int M,
                           int K1, const float* __restrict__ W1,
                           int K2, const float* __restrict__ W2,
                           const float* __restrict__ bias1, const float* __restrict__ bias2,
                           float* __restrict__ out, int ldo, int ooff, float scale) {
    extern __shared__ float sW[];   // O * (K+1), transposed
    int tid = threadIdx.x;
    int K = K1 + K2;
    int KP = K + 1;
    for (int q = tid; q < K1 * O; q += blockDim.x) {
        int k = q / O, o = q - k * O;
        sW[o * KP + k] = W1[q];
    }
    for (int q = tid; q < K2 * O; q += blockDim.x) {
        int k = q / O, o = q - k * O;
        sW[o * KP + K1 + k] = W2[q];
    }
    __syncthreads();

    int wid = tid >> 5;
    int lane = tid & 31;
    int wpb = blockDim.x >> 5;
    for (int warp = blockIdx.x * wpb + wid; warp < M; warp += gridDim.x * wpb) {
        const __half* Ar = A + (size_t)warp * lda;

        float acc[O];
        #pragma unroll
        for (int o = 0; o < O; o++) acc[o] = 0.f;

        for (int k = lane * 2; k < K; k += 64) {
            float2 a = __half22float2(*(const __half2*)(Ar + k));
            #pragma unroll
            for (int o = 0; o < O; o++)
                acc[o] += a.x * sW[o * KP + k] + a.y * sW[o * KP + k + 1];
        }

        float myv = 0.f;
        #pragma unroll
        for (int o = 0; o < O; o++) {
            float v = acc[o];
            v += __shfl_xor_sync(0xffffffffu, v, 16);
            v += __shfl_xor_sync(0xffffffffu, v, 8);
            v += __shfl_xor_sync(0xffffffffu, v, 4);
            v += __shfl_xor_sync(0xffffffffu, v, 2);
            v += __shfl_xor_sync(0xffffffffu, v, 1);
            if (lane == o) myv = v;
        }
        if (lane < O) {
            float r = myv + (bias1 ? bias1[lane] : 0.f) + (bias2 ? bias2[lane] : 0.f);
            out[(size_t)warp * ldo + ooff + lane] = r * scale;
        }
    }
}

// ---------------------------------------------------------------------------
// Host launch
// ---------------------------------------------------------------------------
template <typename T>
static T* symaddr(const void* sym) {
    void* p = nullptr;
    cudaGetSymbolAddress(&p, sym);
    return (T*)p;
}

extern "C" void kernel_launch(void* const* d_in, const int* in_sizes, int n_in,
                              void* d_out, int out_size) {
    cudaFuncSetAttribute(gemm_small<3>, cudaFuncAttributeMaxDynamicSharedMemorySize, 64 * 1024);

    const float* pos       = (const float*)d_in[0];
    const float* vel       = (const float*)d_in[1];
    const float* box       = (const float*)d_in[2];
    const float* box_feats = (const float*)d_in[3];
    const float* cf_w = (const float*)d_in[4];
    const float* cf_b = (const float*)d_in[5];
    const float* co_w = (const float*)d_in[6];
    const float* co_b = (const float*)d_in[7];
    const float* d0_w = (const float*)d_in[8];
    const float* d0_b = (const float*)d_in[9];
    const float* c1_w = (const float*)d_in[10];
    const float* c1_b = (const float*)d_in[11];
    const float* d1_w = (const float*)d_in[12];
    const float* d1_b = (const float*)d_in[13];
    const float* c2_w = (const float*)d_in[14];
    const float* c2_b = (const float*)d_in[15];
    const float* d2_w = (const float*)d_in[16];
    const float* d2_b = (const float*)d_in[17];
    const float* c3_w = (const float*)d_in[18];
    const float* c3_b = (const float*)d_in[19];
    const float* d3_w = (const float*)d_in[20];
    const float* d3_b = (const float*)d_in[21];
    float* out = (float*)d_out;

    __half* S   = symaddr<__half>(g_S);
    float* x96  = symaddr<float>(g_x96);
    float* ya   = symaddr<float>(g_ya);
    float* yb   = symaddr<float>(g_yb);
    float* part = symaddr<float>(g_part);
    __half* Wt1 = symaddr<__half>(g_Wt1);
    __half* Wt2 = symaddr<__half>(g_Wt2);
    int*   fcnt  = symaddr<int>(g_fcnt);
    int*   fidx  = symaddr<int>(g_fidx);
    int*   fcell = symaddr<int>(g_fcell);
    float* fcoef = symaddr<float>(g_fcoef);

    const int M = NQ;

    // 0-2) hash grids
    dim3 gh((NQ + 255) / 256, 2);
    grid_hist2<<<gh, 256>>>(pos, box);                          // idx 0
    grid_scan2<<<2, NCELLS>>>();                                // idx 1
    grid_fill2<<<gh, 256>>>(pos, box);                          // idx 2

    // 3) neighbor search (2 queries/block)
    dim3 gn(NQ / 2, 2);
    dim3 bn(64, 2);
    nbr_grid2<<<gn, bn>>>(pos, box);                            // idx 3

    // 4-5) weight convert + prep
    convertW<<<(K1TOT + K2TOT) / 32, 256>>>(c1_w, d1_w, c2_w, d2_w);
    prep_kernel<<<(NQ + 255) / 256, 256>>>(vel, d0_w, d0_b);

    // 6-7) first block (merged): x96 = [a_co | a_cf | a_d0]
    dim3 gs(NQ, 2);
    scatter_first<<<gs, 128, 32 * 64 * 4 * 4>>>(box_feats);
    dim3 gp(250, 2);
    gemm32_pair<<<gp, 256, 257 * 32 * 4>>>(cf_w, cf_b, co_w, co_b);

    dim3 gg((M + 63) / 64, SPLITK);

    // 8-10) layer 1: ya = S1 @ [c1_w; d1_w] + c1_b + d1_b
    scatter_mma<96><<<NQ, 128>>>(fcnt, fidx, fcell, fcoef, x96, S, K1TOT);
    gemm_hmma_sk<<<gg, 128>>>(S, M, K1TOT, Wt1, part);
    combine4<<<(M * 64 + 255) / 256, 256>>>(part, c1_b, d1_b, nullptr, ya, M);

    // 11-13) layer 2: yb = S2 @ [c2_w; d2_w] + c2_b + d2_b + ya
    scatter_mma<64><<<NQ, 128>>>(fcnt, fidx, fcell, fcoef, ya, S, K2TOT);
    gemm_hmma_sk<<<gg, 128>>>(S, M, K2TOT, Wt2, part);
    combine4<<<(M * 64 + 255) / 256, 256>>>(part, c2_b, d2_b, ya, yb, M);

    // 14-15) layer 3: out = (S3 @ [c3_w; d3_w] + c3_b + d3_b) / 128
    scatter_mma<64><<<NQ, 128>>>(fcnt, fidx, fcell, fcoef, yb, S, K2TOT);
    gemm_small<3><<<256, 256, 4161 * 3 * 4>>>(S, K2TOT, M, 4096, c3_w, 64, d3_w, c3_b, d3_b, out, 3, 0, 1.0f / 128.0f);
}

// round 17
// speedup vs baseline: 1.0508x; 1.0508x over previous
#include <cuda_runtime.h>
#include <cuda_bf16.h>
#include <cuda_fp16.h>
#include <math.h>

// ---------------------------------------------------------------------------
// Problem constants
// ---------------------------------------------------------------------------
#define NQ      6000
#define NBOX    3000
#define KMAX    80
#define CAP     256
#define KS      4
#define NCELL   64
#define RADIUS  0.1125f

#define GDIM    8
#define NCELLS  (GDIM*GDIM*GDIM)

#define K1TOT   6240     // layer1 GEMM K (6144 conv + 96 dense)
#define K2TOT   4160     // layer2 GEMM K (4096 conv + 64 dense)
#define SPLITK  4

// ---------------------------------------------------------------------------
// Device scratch
// ---------------------------------------------------------------------------
__device__ __align__(16) __half g_S[(size_t)NQ * K1TOT];
__device__ __align__(16) float g_x96[NQ * 96];
__device__ __align__(16) float g_ya[NQ * 64];
__device__ __align__(16) float g_yb[NQ * 64];
__device__ __align__(16) float g_ff[NQ * 4];
__device__ __align__(16) float g_part[SPLITK * NQ * 64];
__device__ __align__(16) __half g_Wt1[64 * K1TOT];   // [n][k] fp16, layer1
__device__ __align__(16) __half g_Wt2[64 * K2TOT];   // [n][k] fp16, layer2

__device__ int   g_fcnt[NQ];
__device__ int   g_fidx[NQ * KMAX];
__device__ int   g_fcell[NQ * KMAX];
__device__ __align__(16) float g_fcoef[(size_t)NQ * KMAX * 8];

__device__ int   g_ocnt[NQ];
__device__ int   g_oidx[NQ * KMAX];
__device__ int   g_ocell[NQ * KMAX];
__device__ __align__(16) float g_ocoef[(size_t)NQ * KMAX * 8];

// hash grids (0 = fluid/pos, 1 = box); counters self-re-zeroed in grid_scan2
__device__ int g_gcnt[2][NCELLS];
__device__ int g_gstart[2][NCELLS + 1];
__device__ int g_gcur[2][NCELLS];
__device__ int g_glistF[NQ];
__device__ int g_glistB[NBOX];

// ---------------------------------------------------------------------------
// Helpers
// ---------------------------------------------------------------------------
__device__ __forceinline__ float fsign(float x) {
    return (x > 0.f) ? 1.f : ((x < 0.f) ? -1.f : 0.f);
}

__device__ __forceinline__ int cell_coord(float x) {
    int c = (int)(x * (float)GDIM);
    return min(max(c, 0), GDIM - 1);
}

__device__ __forceinline__ void mma16816(float4& d, unsigned a0, unsigned a1,
                                         unsigned a2, unsigned a3,
                                         unsigned b0, unsigned b1) {
    asm volatile(
        "mma.sync.aligned.m16n8k16.row.col.f32.f16.f16.f32 "
        "{%0,%1,%2,%3}, {%4,%5,%6,%7}, {%8,%9}, {%0,%1,%2,%3};"
        : "+f"(d.x), "+f"(d.y), "+f"(d.z), "+f"(d.w)
        : "r"(a0), "r"(a1), "r"(a2), "r"(a3), "r"(b0), "r"(b1));
}

// ---------------------------------------------------------------------------
// Hash grid build
// ---------------------------------------------------------------------------
__global__ void grid_hist2(const float* __restrict__ pos, const float* __restrict__ box) {
    int g = blockIdx.y;
    const float* p = g ? box : pos;
    int n = g ? NBOX : NQ;
    int i = blockIdx.x * blockDim.x + threadIdx.x;
    if (i >= n) return;
    int cx = cell_coord(p[3 * i + 0]);
    int cy = cell_coord(p[3 * i + 1]);
    int cz = cell_coord(p[3 * i + 2]);
    atomicAdd(&g_gcnt[g][(cz * GDIM + cy) * GDIM + cx], 1);
}

__global__ void grid_scan2() {
    int g = blockIdx.x;
    __shared__ int s[NCELLS];
    int t = threadIdx.x;
    int v = g_gcnt[g][t];
    g_gcnt[g][t] = 0;          // reset for next replay (deterministic)
    s[t] = v;
    __syncthreads();
    for (int off = 1; off < NCELLS; off <<= 1) {
        int x = (t >= off) ? s[t - off] : 0;
        __syncthreads();
        s[t] += x;
        __syncthreads();
    }
    g_gstart[g][t + 1] = s[t];
    g_gcur[g][t] = s[t] - v;
    if (t == 0) g_gstart[g][0] = 0;
}

__global__ void grid_fill2(const float* __restrict__ pos, const float* __restrict__ box) {
    int g = blockIdx.y;
    const float* p = g ? box : pos;
    int n = g ? NBOX : NQ;
    int* list = g ? g_glistB : g_glistF;
    int i = blockIdx.x * blockDim.x + threadIdx.x;
    if (i >= n) return;
    int cx = cell_coord(p[3 * i + 0]);
    int cy = cell_coord(p[3 * i + 1]);
    int cz = cell_coord(p[3 * i + 2]);
    int slot = atomicAdd(&g_gcur[g][(cz * GDIM + cy) * GDIM + cx], 1);
    list[slot] = i;
}

// ---------------------------------------------------------------------------
// Neighbor search: 2 queries per block (threadIdx.y), both passes on blockIdx.y.
// blockDim (64, 2), grid (NQ/2, 2).   [measured WIN in R16: 31.4 -> 24.8 us]
// ---------------------------------------------------------------------------
__global__ void nbr_grid2(const float* __restrict__ pos, const float* __restrict__ box) {
    int pass = blockIdx.y;
    const float* pin   = pass ? box : pos;
    const int*  glist  = pass ? g_glistB : g_glistF;
    const int*  gstart = g_gstart[pass];
    int selfExcl = pass ? 0 : 1;
    int* cnt_out  = pass ? g_ocnt  : g_fcnt;
    int* idx_out  = pass ? g_oidx  : g_fidx;
    int* cell_out = pass ? g_ocell : g_fcell;
    float* coef_out = pass ? g_ocoef : g_fcoef;

    int qy = threadIdx.y;                     // 0 or 1
    int i = blockIdx.x * 2 + qy;              // query index
    __shared__ float sd2[2][CAP];
    __shared__ int   sj[2][CAP];
    __shared__ int   ssel[2][KMAX];
    __shared__ int   scnt[2], skeep[2];
    int tid = threadIdx.x;
    const int NT = 64;
    if (tid == 0) { scnt[qy] = 0; skeep[qy] = 0; }
    __syncthreads();

    float qx = pos[3 * i + 0], qyc = pos[3 * i + 1], qz = pos[3 * i + 2];
    const float R2 = RADIUS * RADIUS;

    int cx = cell_coord(qx), cy = cell_coord(qyc), cz = cell_coord(qz);
    int x0 = max(cx - 1, 0), x1 = min(cx + 1, GDIM - 1);
    int y0 = max(cy - 1, 0), y1 = min(cy + 1, GDIM - 1);
    int z0 = max(cz - 1, 0), z1 = min(cz + 1, GDIM - 1);

    for (int z = z0; z <= z1; z++) {
        for (int y = y0; y <= y1; y++) {
            int cbase = (z * GDIM + y) * GDIM;
            int b = gstart[cbase + x0];
            int e = gstart[cbase + x1 + 1];
            for (int t = b + tid; t < e; t += NT) {
                int j = glist[t];
                if (selfExcl && j == i) continue;
                float dx = pin[3 * j + 0] - qx;
                float dy = pin[3 * j + 1] - qyc;
                float dz = pin[3 * j + 2] - qz;
                float d2 = dx * dx + dy * dy + dz * dz;
                if (d2 <= R2) {
                    int p = atomicAdd(&scnt[qy], 1);
                    if (p < CAP) { sd2[qy][p] = d2; sj[qy][p] = j; }
                }
            }
        }
    }
    __syncthreads();

    int cnt = min(scnt[qy], CAP);
    int kcnt;
    if (cnt <= KMAX) {
        kcnt = cnt;
        for (int e = tid; e < cnt; e += NT) ssel[qy][e] = sj[qy][e];
    } else {
        kcnt = KMAX;
        for (int e = tid; e < cnt; e += NT) {
            float m2 = sd2[qy][e]; int mj = sj[qy][e]; int rank = 0;
            for (int q = 0; q < cnt; q++) {
                float o2 = sd2[qy][q];
                rank += (o2 < m2) || (o2 == m2 && sj[qy][q] < mj);
            }
            if (rank < KMAX) { int p = atomicAdd(&skeep[qy], 1); ssel[qy][p] = mj; }
        }
    }
    __syncthreads();
    if (tid == 0) cnt_out[i] = kcnt;

    const float EPS = 1e-12f;
    const float FP  = (float)(4.0 / 3.14159265358979323846);

    for (int k = tid; k < kcnt; k += NT) {
        int j = ssel[qy][k];
        float rx = (pin[3 * j + 0] - qx) / RADIUS;
        float ry = (pin[3 * j + 1] - qyc) / RADIUS;
        float rz = (pin[3 * j + 2] - qz) / RADIUS;

        float sq = rx * rx + ry * ry + rz * rz;
        float p1m = 1.0f - sq;
        float win = p1m * p1m * p1m;
        win = fminf(fmaxf(win, 0.f), 1.f);

        float nrm  = sqrtf(sq);
        float rxy2 = rx * rx + ry * ry;
        bool  polar = (1.25f * rz * rz) > rxy2;
        float s_pol = sqrtf(3.0f * nrm / (nrm + fabsf(rz) + EPS));
        float s_eq  = nrm / sqrtf(rxy2 + EPS);
        float xc = polar ? s_pol * rx : s_eq * rx;
        float yc = polar ? s_pol * ry : s_eq * ry;
        float zc = polar ? fsign(rz) * nrm : 1.5f * rz * s_eq;
        if (sq < 1e-12f) { xc = 0.f; yc = 0.f; zc = 0.f; }

        float rxy = sqrtf(xc * xc + yc * yc);
        float sx = (fabsf(xc) < EPS) ? EPS : xc;
        float sy = (fabsf(yc) < EPS) ? EPS : yc;
        float u1 = fsign(xc) * rxy;
        float v1 = u1 * FP * atanf(yc / sx);
        float v2 = fsign(yc) * rxy;
        float u2 = v2 * FP * atanf(xc / sy);
        float u, v;
        if (fabsf(xc) >= fabsf(yc)) { u = u1; v = v1; } else { u = u2; v = v2; }
        if (rxy < EPS) { u = 0.f; v = 0.f; }

        float gx = fminf(fmaxf((u  + 1.0f) * 0.5f * (float)(KS - 1), 0.f), (float)(KS - 1));
        float gy = fminf(fmaxf((v  + 1.0f) * 0.5f * (float)(KS - 1), 0.f), (float)(KS - 1));
        float gz = fminf(fmaxf((zc + 1.0f) * 0.5f * (float)(KS - 1), 0.f), (float)(KS - 1));
        int ix = min((int)floorf(gx), KS - 2);
        int iy = min((int)floorf(gy), KS - 2);
        int iz = min((int)floorf(gz), KS - 2);
        float tx = gx - (float)ix, ty = gy - (float)iy, tz = gz - (float)iz;

        int slot = i * KMAX + k;
        idx_out[slot]  = j;
        cell_out[slot] = (iz * KS + iy) * KS + ix;

        float wx[2] = {1.f - tx, tx};
        float wy[2] = {1.f - ty, ty};
        float wz[2] = {1.f - tz, tz};
        float* cf = coef_out + (size_t)slot * 8;
        #pragma unroll
        for (int dx = 0; dx < 2; dx++)
            #pragma unroll
            for (int dy = 0; dy < 2; dy++)
                #pragma unroll
                for (int dz = 0; dz < 2; dz++)
                    cf[dx * 4 + dy * 2 + dz] = wx[dx] * wy[dy] * wz[dz] * win;
    }
}

// ---------------------------------------------------------------------------
// convertW: build fp16 transposed weights Wt[n][k] for both HMMA layers.
// ---------------------------------------------------------------------------
__global__ void convertW(const float* __restrict__ c1w, const float* __restrict__ d1w,
                         const float* __restrict__ c2w, const float* __restrict__ d2w) {
    __shared__ float s[32][65];
    int t = blockIdx.x;
    const float *Wa, *Wb;
    __half* Wt;
    int K, Ka, k0;
    if (t < K1TOT / 32) {
        k0 = t * 32; K = K1TOT; Ka = 6144; Wa = c1w; Wb = d1w; Wt = g_Wt1;
    } else {
        k0 = (t - K1TOT / 32) * 32; K = K2TOT; Ka = 4096; Wa = c2w; Wb = d2w; Wt = g_Wt2;
    }
    int tid = threadIdx.x;
    #pragma unroll
    for (int i = 0; i < 8; i++) {
        int idx = tid + i * 256;          // 0..2047
        int row = idx >> 6;               // k offset 0..31
        int col = idx & 63;               // n
        int k = k0 + row;
        float v = (k < Ka) ? Wa[(size_t)k * 64 + col] : Wb[(size_t)(k - Ka) * 64 + col];
        s[row][col] = v;
    }
    __syncthreads();
    #pragma unroll
    for (int i = 0; i < 8; i++) {
        int idx = tid + i * 256;
        int n  = idx >> 5;                // 0..63
        int kk = idx & 31;
        Wt[(size_t)n * K + k0 + kk] = __float2half_rn(s[kk][n]);
    }
}

// ---------------------------------------------------------------------------
// prep: ff = [1,vel]; x96[:,64:96] = ff @ d0_w + d0_b
// ---------------------------------------------------------------------------
__global__ void prep_kernel(const float* __restrict__ vel,
                            const float* __restrict__ d0_w, const float* __restrict__ d0_b) {
    int i = blockIdx.x * blockDim.x + threadIdx.x;
    if (i >= NQ) return;
    float f1 = vel[i * 3 + 0], f2 = vel[i * 3 + 1], f3 = vel[i * 3 + 2];
    g_ff[i * 4 + 0] = 1.0f;
    g_ff[i * 4 + 1] = f1;
    g_ff[i * 4 + 2] = f2;
    g_ff[i * 4 + 3] = f3;
    #pragma unroll 8
    for (int o = 0; o < 32; o++) {
        g_x96[i * 96 + 64 + o] = d0_w[o] + f1 * d0_w[32 + o] + f2 * d0_w[64 + o]
                                 + f3 * d0_w[96 + o] + d0_b[o];
    }
}

// ---------------------------------------------------------------------------
// Merged first-block scatter: y=0 fluid/ff (F=4), y=1 box/box_feats (F=3).
// ---------------------------------------------------------------------------
__global__ void scatter_first(const float* __restrict__ box_feats) {
    int pass = blockIdx.y;
    const int F = pass ? 3 : 4;
    const int nF = 64 * F;
    const float* feats = pass ? box_feats : g_ff;
    const int* cnt  = pass ? g_ocnt  : g_fcnt;
    const int* nidx = pass ? g_oidx  : g_fidx;
    const int* ncel = pass ? g_ocell : g_fcell;
    const float* ncoef = pass ? g_ocoef : g_fcoef;
    __half* dst = g_S + (pass ? (size_t)NQ * 256 : 0);
    int ldS = pass ? 192 : 256;

    int i = blockIdx.x;
    extern __shared__ float shS[];            // 32 * nF floats (<= 32KB)
    __shared__ float shC[KMAX * 8];
    __shared__ int   shI[KMAX];
    __shared__ int   shCe[KMAX];
    int tid = threadIdx.x;
    const int NT = 128;

    for (int q = tid; q < 32 * nF; q += NT) shS[q] = 0.f;
    int c = cnt[i];
    for (int q = tid; q < c; q += NT) {
        shI[q]  = nidx[i * KMAX + q];
        shCe[q] = ncel[i * KMAX + q];
    }
    for (int q = tid; q < c * 8; q += NT)
        shC[q] = ncoef[(size_t)i * KMAX * 8 + q];
    __syncthreads();

    {
        int f = tid % F;
        int s = tid / F;
        if (s < 32) {
            int k0 = (c * s) / 32;
            int k1 = (c * (s + 1)) / 32;
            float* my = shS + s * nF;
            const int OFF[8] = {0, 16, 4, 20, 1, 17, 5, 21};
            for (int k = k0; k < k1; k++) {
                int j = shI[k];
                float vv = feats[(size_t)j * F + f];
                int base = shCe[k] * F + f;
                #pragma unroll
                for (int cc = 0; cc < 8; cc++)
                    my[base + OFF[cc] * F] += shC[k * 8 + cc] * vv;
            }
        }
    }
    __syncthreads();

    __half* drow = dst + (size_t)i * ldS;
    for (int q = tid * 2; q < nF; q += NT * 2) {
        float v0 = shS[q], v1 = shS[q + 1];
        #pragma unroll
        for (int s = 1; s < 32; s++) { v0 += shS[s * nF + q]; v1 += shS[s * nF + q + 1]; }
        *(__half2*)(drow + q) = __floats2half2_rn(v0, v1);
    }
}

// ---------------------------------------------------------------------------
// Non-persistent 32-col GEMM pair (R15 form): y=0 cf (K=256), y=1 co (K=192).
// ---------------------------------------------------------------------------
__global__ void gemm32_pair(const float* __restrict__ cf_w, const float* __restrict__ cf_b,
                            const float* __restrict__ co_w, const float* __restrict__ co_b) {
    int pass = blockIdx.y;
    int K = pass ? 192 : 256;
    const __half* A = g_S + (pass ? (size_t)NQ * 256 : 0);
    const float* W = pass ? co_w : cf_w;
    const float* b = pass ? co_b : cf_b;
    int ooff = pass ? 0 : 32;

    extern __shared__ float sW[];   // 32 * (K+1)
    int tid = threadIdx.x;
    int KP = K + 1;
    for (int q = tid; q < K * 32; q += blockDim.x) {
        int k = q >> 5, o = q & 31;
        sW[o * KP + k] = W[q];
    }
    __syncthreads();

    int warp = blockIdx.x * 8 + (tid >> 5);
    int lane = tid & 31;
    if (warp >= NQ) return;
    const __half* Ar = A + (size_t)warp * K;

    float acc[32];
    #pragma unroll
    for (int o = 0; o < 32; o++) acc[o] = 0.f;

    for (int k = lane * 2; k < K; k += 64) {
        float2 a = __half22float2(*(const __half2*)(Ar + k));
        #pragma unroll
        for (int o = 0; o < 32; o++)
            acc[o] += a.x * sW[o * KP + k] + a.y * sW[o * KP + k + 1];
    }

    float myv = 0.f;
    #pragma unroll
    for (int o = 0; o < 32; o++) {
        float v = acc[o];
        v += __shfl_xor_sync(0xffffffffu, v, 16);
        v += __shfl_xor_sync(0xffffffffu, v, 8);
        v += __shfl_xor_sync(0xffffffffu, v, 4);
        v += __shfl_xor_sync(0xffffffffu, v, 2);
        v += __shfl_xor_sync(0xffffffffu, v, 1);
        if (lane == o) myv = v;
    }
    g_x96[(size_t)warp * 96 + ooff + lane] = myv + b[lane];
}

// ---------------------------------------------------------------------------
// Tensor-core scatter: S_row[64,F] = CoefDense[64,80] @ NF[80,F] per particle.
// k-loop dynamically bounded at climit = ceil16(c).
// ---------------------------------------------------------------------------
#define PA 82   // smem pitch in halves (41 words)

template <int F>
__global__ void scatter_mma(const int* __restrict__ cnt, const int* __restrict__ nidx,
                            const int* __restrict__ ncell, const float* __restrict__ ncoef,
                            const float* __restrict__ feats,
                            __half* __restrict__ Sout, int ldS) {
    __shared__ __half sA[64 * PA];      // coef dense [cell][k]
    __shared__ __half sB[F * PA];       // feats transposed [f][k]
    __shared__ float shC[KMAX * 8];
    __shared__ int   shI[KMAX];

    int i = blockIdx.x;
    int tid = threadIdx.x;
    int warp = tid >> 5, lane = tid & 31;
    int g = lane >> 2, tq = lane & 3;

    int c = cnt[i];
    int climit = (c + 15) & ~15;        // MMA k-range (multiple of 16, <= 80)
    int words = climit >> 1;            // half2 words per row to zero

    unsigned* za = (unsigned*)sA;
    unsigned* zb = (unsigned*)sB;
    for (int q = tid; q < 64 * words; q += 128) {
        int r = q / words, w = q - r * words;
        za[r * (PA / 2) + w] = 0u;
    }
    for (int q = tid; q < F * words; q += 128) {
        int r = q / words, w = q - r * words;
        zb[r * (PA / 2) + w] = 0u;
    }

    for (int q = tid; q < c; q += 128) shI[q] = nidx[i * KMAX + q];
    for (int q = tid; q < c * 8; q += 128) shC[q] = ncoef[(size_t)i * KMAX * 8 + q];
    __syncthreads();

    {
        const int OFF[8] = {0, 16, 4, 20, 1, 17, 5, 21};
        __shared__ int shCe[KMAX];
        for (int q = tid; q < c; q += 128) shCe[q] = ncell[i * KMAX + q];
        __syncthreads();
        for (int t = tid; t < c * 8; t += 128) {
            int k = t >> 3, cc = t & 7;
            sA[(shCe[k] + OFF[cc]) * PA + k] = __float2half_rn(shC[t]);
        }
    }

    for (int k = warp; k < c; k += 4) {
        const float* fr = feats + (size_t)shI[k] * F;
        #pragma unroll
        for (int f = lane; f < F; f += 32)
            sB[f * PA + k] = __float2half_rn(fmaxf(fr[f], 0.f));
    }
    __syncthreads();

    float4 acc[F / 8];
    #pragma unroll
    for (int nj = 0; nj < F / 8; nj++) acc[nj] = make_float4(0.f, 0.f, 0.f, 0.f);

    for (int ks = 0; ks < climit; ks += 16) {
        int rbase = (warp * 16 + g) * PA + ks + 2 * tq;
        unsigned a0 = *(const unsigned*)&sA[rbase];
        unsigned a1 = *(const unsigned*)&sA[rbase + 8 * PA];
        unsigned a2 = *(const unsigned*)&sA[rbase + 8];
        unsigned a3 = *(const unsigned*)&sA[rbase + 8 * PA + 8];
        #pragma unroll
        for (int nj = 0; nj < F / 8; nj++) {
            int nbase = (nj * 8 + g) * PA + ks + 2 * tq;
            unsigned b0 = *(const unsigned*)&sB[nbase];
            unsigned b1 = *(const unsigned*)&sB[nbase + 8];
            mma16816(acc[nj], a0, a1, a2, a3, b0, b1);
        }
    }

    __half* dst = Sout + (size_t)i * ldS;
    int r0 = warp * 16 + g, r1 = r0 + 8;
    #pragma unroll
    for (int nj = 0; nj < F / 8; nj++) {
        int col = nj * 8 + 2 * tq;
        *(__half2*)(dst + r0 * F + col) = __floats2half2_rn(acc[nj].x, acc[nj].y);
        *(__half2*)(dst + r1 * F + col) = __floats2half2_rn(acc[nj].z, acc[nj].w);
    }
    if (tid < F)
        dst[64 * F + tid] = __float2half_rn(fmaxf(feats[(size_t)i * F + tid], 0.f));
}

// ---------------------------------------------------------------------------
// HMMA GEMM with split-K: grid (ceil(M/64), SPLITK). Raw partials to part.
// ---------------------------------------------------------------------------
#define PITCH 40

__global__ void gemm_hmma_sk(const __half* __restrict__ A, int M, int K,
                             const __half* __restrict__ Wt,
                             float* __restrict__ part) {
    __shared__ __half sA[2][64 * PITCH];
    __shared__ __half sB[2][64 * PITCH];

    int tid = threadIdx.x;
    int warp = tid >> 5, lane = tid & 31;
    int g = lane >> 2, tq = lane & 3;
    int wm = (warp & 1) * 32, wn = (warp >> 1) * 32;
    int bm = blockIdx.x * 64;

    int nt = K / 32;
    int tps = (nt + SPLITK - 1) / SPLITK;
    int t0 = blockIdx.y * tps;
    int t1 = min(t0 + tps, nt);
    float* out = part + (size_t)blockIdx.y * M * 64;

    int c0 = tid * 2, c1 = c0 + 1;
    int rA0 = c0 >> 2, ch0 = c0 & 3;
    int rA1 = c1 >> 2, ch1 = c1 & 3;
    bool ok0 = (bm + rA0) < M, ok1 = (bm + rA1) < M;
    const __half* Ab0 = A + (size_t)(bm + rA0) * K + ch0 * 8;
    const __half* Ab1 = A + (size_t)(bm + rA1) * K + ch1 * 8;
    const __half* Wb0 = Wt + (size_t)rA0 * K + ch0 * 8;
    const __half* Wb1 = Wt + (size_t)rA1 * K + ch1 * 8;

    float4 acc[2][4];
    #pragma unroll
    for (int i = 0; i < 2; i++)
        #pragma unroll
        for (int j = 0; j < 4; j++) acc[i][j] = make_float4(0.f, 0.f, 0.f, 0.f);

    const uint4 Z = make_uint4(0u, 0u, 0u, 0u);
    uint4 ra0, ra1, rb0, rb1;

    {
        int kt = t0 * 32;
        ra0 = ok0 ? *(const uint4*)(Ab0 + kt) : Z;
        ra1 = ok1 ? *(const uint4*)(Ab1 + kt) : Z;
        rb0 = *(const uint4*)(Wb0 + kt);
        rb1 = *(const uint4*)(Wb1 + kt);
    }
    *(uint4*)&sA[0][rA0 * PITCH + ch0 * 8] = ra0;
    *(uint4*)&sA[0][rA1 * PITCH + ch1 * 8] = ra1;
    *(uint4*)&sB[0][rA0 * PITCH + ch0 * 8] = rb0;
    *(uint4*)&sB[0][rA1 * PITCH + ch1 * 8] = rb1;
    __syncthreads();

    for (int t = t0; t < t1; t++) {
        int cur = (t - t0) & 1;
        if (t + 1 < t1) {
            int kt = (t + 1) * 32;
            ra0 = ok0 ? *(const uint4*)(Ab0 + kt) : Z;
            ra1 = ok1 ? *(const uint4*)(Ab1 + kt) : Z;
            rb0 = *(const uint4*)(Wb0 + kt);
            rb1 = *(const uint4*)(Wb1 + kt);
        }

        const __half* cA = sA[cur];
        const __half* cB = sB[cur];
        #pragma unroll
        for (int ks = 0; ks < 32; ks += 16) {
            unsigned af[2][4], bf[4][2];
            #pragma unroll
            for (int mi = 0; mi < 2; mi++) {
                int rbase = (wm + mi * 16 + g) * PITCH + ks + 2 * tq;
                af[mi][0] = *(const unsigned*)&cA[rbase];
                af[mi][1] = *(const unsigned*)&cA[rbase + 8 * PITCH];
                af[mi][2] = *(const unsigned*)&cA[rbase + 8];
                af[mi][3] = *(const unsigned*)&cA[rbase + 8 * PITCH + 8];
            }
            #pragma unroll
            for (int nj = 0; nj < 4; nj++) {
                int nbase = (wn + nj * 8 + g) * PITCH + ks + 2 * tq;
                bf[nj][0] = *(const unsigned*)&cB[nbase];
                bf[nj][1] = *(const unsigned*)&cB[nbase + 8];
            }
            #pragma unroll
            for (int mi = 0; mi < 2; mi++)
                #pragma unroll
                for (int nj = 0; nj < 4; nj++)
                    mma16816(acc[mi][nj], af[mi][0], af[mi][1], af[mi][2], af[mi][3],
                             bf[nj][0], bf[nj][1]);
        }

        if (t + 1 < t1) {
            int nxt = cur ^ 1;
            *(uint4*)&sA[nxt][rA0 * PITCH + ch0 * 8] = ra0;
            *(uint4*)&sA[nxt][rA1 * PITCH + ch1 * 8] = ra1;
            *(uint4*)&sB[nxt][rA0 * PITCH + ch0 * 8] = rb0;
            *(uint4*)&sB[nxt][rA1 * PITCH + ch1 * 8] = rb1;
            __syncthreads();
        }
    }

    #pragma unroll
    for (int mi = 0; mi < 2; mi++) {
        int r0 = bm + wm + mi * 16 + g;
        int r1 = r0 + 8;
        #pragma unroll
        for (int nj = 0; nj < 4; nj++) {
            int col = wn + nj * 8 + 2 * tq;
            float4 d = acc[mi][nj];
            if (r0 < M) *(float2*)&out[(size_t)r0 * 64 + col] = make_float2(d.x, d.y);
            if (r1 < M) *(float2*)&out[(size_t)r1 * 64 + col] = make_float2(d.z, d.w);
        }
    }
}

// ---------------------------------------------------------------------------
// combine4: out = sum(4 partials) + b1 + b2 (+ res)
// ---------------------------------------------------------------------------
__global__ void combine4(const float* __restrict__ part,
                         const float* __restrict__ b1, const float* __restrict__ b2,
                         const float* __restrict__ res, float* __restrict__ out, int M) {
    int idx = blockIdx.x * blockDim.x + threadIdx.x;
    if (idx >= M * 64) return;
    int c = idx & 63;
    size_t st = (size_t)M * 64;
    float v = part[idx] + part[st + idx] + part[2 * st + idx] + part[3 * st + idx]
              + b1[c] + b2[c];
    if (res) v += res[idx];
    out[idx] = v;
}

// ---------------------------------------------------------------------------
// Non-persistent small-O GEMM (R15 form), fp16 A, transposed W cache [O][K+1].
// ---------------------------------------------------------------------------
template <int O>
__global__ void gemm_small(const __half* __restrict__ A, int lda, int M,
                           int K1, const float* __restrict__ W1,
                           int K2, const float* __restrict__ W2,
                           const float* __restrict__ bias1, const float* __restrict__ bias2,
                           float* __restrict__ out, int ldo, int ooff, float scale) {
    extern __shared__ float sW[];   // O * (K+1), transposed
    int tid = threadIdx.x;
    int K = K1 + K2;
    int KP = K + 1;
    for (int q = tid; q < K1 * O; q += blockDim.x) {
        int k = q / O, o = q - k * O;
        sW[o * KP + k] = W1[q];
    }
    for (int q = tid; q < K2 * O; q += blockDim.x) {
        int k = q / O, o = q - k * O;
        sW[o * KP + K1 + k] = W2[q];
    }
    __syncthreads();

    int warp = blockIdx.x * (blockDim.x >> 5) + (tid >> 5);
    int lane = tid & 31;
    if (warp >= M) return;
    const __half* Ar = A + (size_t)warp * lda;

    float acc[O];
    #pragma unroll
    for (int o = 0; o < O; o++) acc[o] = 0.f;

    for (int k = lane * 2; k < K; k += 64) {
        float2 a = __half22float2(*(const __half2*)(Ar + k));
        #pragma unroll
        for (int o = 0; o < O; o++)
            acc[o] += a.x * sW[o * KP + k] + a.y * sW[o * KP + k + 1];
    }

    float myv = 0.f;
    #pragma unroll
    for (int o = 0; o < O; o++) {
        float v = acc[o];
        v += __shfl_xor_sync(0xffffffffu, v, 16);
        v += __shfl_xor_sync(0xffffffffu, v, 8);
        v += __shfl_xor_sync(0xffffffffu, v, 4);
        v += __shfl_xor_sync(0xffffffffu, v, 2);
        v += __shfl_xor_sync(0xffffffffu, v, 1);
        if (lane == o) myv = v;
    }
    if (lane < O) {
        float r = myv + (bias1 ? bias1[lane] : 0.f) + (bias2 ? bias2[lane] : 0.f);
        out[(size_t)warp * ldo + ooff + lane] = r * scale;
    }
}

// ---------------------------------------------------------------------------
// Host launch
// ---------------------------------------------------------------------------
template <typename T>
static T* symaddr(const void* sym) {
    void* p = nullptr;
    cudaGetSymbolAddress(&p, sym);
    return (T*)p;
}

extern "C" void kernel_launch(void* const* d_in, const int* in_sizes, int n_in,
                              void* d_out, int out_size) {
    cudaFuncSetAttribute(gemm_small<3>, cudaFuncAttributeMaxDynamicSharedMemorySize, 64 * 1024);

    const float* pos       = (const float*)d_in[0];
    const float* vel       = (const float*)d_in[1];
    const float* box       = (const float*)d_in[2];
    const float* box_feats = (const float*)d_in[3];
    const float* cf_w = (const float*)d_in[4];
    const float* cf_b = (const float*)d_in[5];
    const float* co_w = (const float*)d_in[6];
    const float* co_b = (const float*)d_in[7];
    const float* d0_w = (const float*)d_in[8];
    const float* d0_b = (const float*)d_in[9];
    const float* c1_w = (const float*)d_in[10];
    const float* c1_b = (const float*)d_in[11];
    const float* d1_w = (const float*)d_in[12];
    const float* d1_b = (const float*)d_in[13];
    const float* c2_w = (const float*)d_in[14];
    const float* c2_b = (const float*)d_in[15];
    const float* d2_w = (const float*)d_in[16];
    const float* d2_b = (const float*)d_in[17];
    const float* c3_w = (const float*)d_in[18];
    const float* c3_b = (const float*)d_in[19];
    const float* d3_w = (const float*)d_in[20];
    const float* d3_b = (const float*)d_in[21];
    float* out = (float*)d_out;

    __half* S   = symaddr<__half>(g_S);
    float* x96  = symaddr<float>(g_x96);
    float* ya   = symaddr<float>(g_ya);
    float* yb   = symaddr<float>(g_yb);
    float* part = symaddr<float>(g_part);
    __half* Wt1 = symaddr<__half>(g_Wt1);
    __half* Wt2 = symaddr<__half>(g_Wt2);
    int*   fcnt  = symaddr<int>(g_fcnt);
    int*   fidx  = symaddr<int>(g_fidx);
    int*   fcell = symaddr<int>(g_fcell);
    float* fcoef = symaddr<float>(g_fcoef);

    const int M = NQ;

    // 0-2) hash grids
    dim3 gh((NQ + 255) / 256, 2);
    grid_hist2<<<gh, 256>>>(pos, box);                          // idx 0
    grid_scan2<<<2, NCELLS>>>();                                // idx 1
    grid_fill2<<<gh, 256>>>(pos, box);                          // idx 2

    // 3) neighbor search (2 queries/block — measured win)
    dim3 gn(NQ / 2, 2);
    dim3 bn(64, 2);
    nbr_grid2<<<gn, bn>>>(pos, box);                            // idx 3

    // 4-5) weight convert + prep
    convertW<<<(K1TOT + K2TOT) / 32, 256>>>(c1_w, d1_w, c2_w, d2_w);
    prep_kernel<<<(NQ + 255) / 256, 256>>>(vel, d0_w, d0_b);

    // 6-7) first block (merged): x96 = [a_co | a_cf | a_d0]
    dim3 gs(NQ, 2);
    scatter_first<<<gs, 128, 32 * 64 * 4 * 4>>>(box_feats);
    dim3 gp((M + 7) / 8, 2);
    gemm32_pair<<<gp, 256, 257 * 32 * 4>>>(cf_w, cf_b, co_w, co_b);

    dim3 gg((M + 63) / 64, SPLITK);

    // 8-10) layer 1: ya = S1 @ [c1_w; d1_w] + c1_b + d1_b
    scatter_mma<96><<<NQ, 128>>>(fcnt, fidx, fcell, fcoef, x96, S, K1TOT);
    gemm_hmma_sk<<<gg, 128>>>(S, M, K1TOT, Wt1, part);
    combine4<<<(M * 64 + 255) / 256, 256>>>(part, c1_b, d1_b, nullptr, ya, M);

    // 11-13) layer 2: yb = S2 @ [c2_w; d2_w] + c2_b + d2_b + ya
    scatter_mma<64><<<NQ, 128>>>(fcnt, fidx, fcell, fcoef, ya, S, K2TOT);
    gemm_hmma_sk<<<gg, 128>>>(S, M, K2TOT, Wt2, part);
    combine4<<<(M * 64 + 255) / 256, 256>>>(part, c2_b, d2_b, ya, yb, M);

    // 14-15) layer 3: out = (S3 @ [c3_w; d3_w] + c3_b + d3_b) / 128
    scatter_mma<64><<<NQ, 128>>>(fcnt, fidx, fcell, fcoef, yb, S, K2TOT);
    gemm_small<3><<<(M + 7) / 8, 256, 4161 * 3 * 4>>>(S, K2TOT, M, 4096, c3_w, 64, d3_w, c3_b, d3_b, out, 3, 0, 1.0f / 128.0f);
}